// round 3
// baseline (speedup 1.0000x reference)
#include <cuda_runtime.h>
#include <cooperative_groups.h>
#include <cstdint>

namespace cg = cooperative_groups;

// Fixed shapes per reference: B=256, L=512, N=50000
constexpr int B_SZ    = 256;
constexpr int L_SEQ   = 512;
constexpr int N_LOC   = 50000;
constexpr int HSIZE   = 1024;          // hash slots (power of 2), load factor <= 0.5
constexpr int SEGS    = 8;             // column segments per row == cluster size
constexpr int SEG_LEN = 6256;          // 8*6256 = 50048 >= 50000; 50000/4 divides cleanly
constexpr int CAP     = 512;           // worst case: all distinct keys in one segment
constexpr int NT      = 256;
constexpr int T_PER_CTA = L_SEQ / SEGS; // 64 timesteps inserted per CTA

__global__ __launch_bounds__(NT) __cluster_dims__(SEGS, 1, 1)
void fused_kernel(const int* __restrict__ loc_seq,
                  const int* __restrict__ mask,
                  const float* __restrict__ rw_p,
                  const float* __restrict__ fw_p,
                  float* __restrict__ out)
{
    cg::cluster_group cluster = cg::this_cluster();
    const int seg = (int)cluster.block_rank();      // 0..7
    const int b   = blockIdx.x / SEGS;
    const int tid = threadIdx.x;

    // Hash lives in rank-0's smem only (others' copies unused but reserved).
    __shared__ int      h_key[HSIZE];
    __shared__ int      h_cnt[HSIZE];
    __shared__ unsigned h_rec[HSIZE];   // float bits; all values >= 0
    __shared__ int      s_maxcnt;
    // Per-CTA receive buffer for compacted (key,val) of this segment.
    __shared__ int      s_n;
    __shared__ int      s_skey[CAP];
    __shared__ float    s_sval[CAP];

    // ---- init (rank 0: hash; everyone: own counter) ----
    if (seg == 0) {
        #pragma unroll 4
        for (int i = tid; i < HSIZE; i += NT) {
            h_key[i] = -1;
            h_cnt[i] = 0;
            h_rec[i] = 0u;
        }
        if (tid == 0) s_maxcnt = 0;
    }
    if (tid == 0) s_n = 0;

    // ---- zero-fill own output segment (bulk of the work, overlaps init) ----
    const int col0 = seg * SEG_LEN;
    const int col1 = min(col0 + SEG_LEN, N_LOC);
    float*  row  = out + (size_t)b * N_LOC;
    float4* row4 = reinterpret_cast<float4*>(row);
    const float4 z = make_float4(0.f, 0.f, 0.f, 0.f);
    #pragma unroll 2
    for (int i = col0 / 4 + tid; i < col1 / 4; i += NT)
        row4[i] = z;

    cluster.sync();   // hash + counters initialized everywhere

    // ---- insert this CTA's 64 timesteps into rank-0's hash (remote atomics) ----
    int*      r_key = cluster.map_shared_rank(h_key, 0);
    int*      r_cnt = cluster.map_shared_rank(h_cnt, 0);
    unsigned* r_rec = cluster.map_shared_rank(h_rec, 0);

    if (tid < T_PER_CTA) {
        const int t   = seg * T_PER_CTA + tid;
        const int key = loc_seq[(size_t)b * L_SEQ + t];
        const int m   = mask   [(size_t)b * L_SEQ + t];
        const float rec = m ? exp2f((float)(L_SEQ - 1 - t) * log2f(*rw_p)) : 0.0f;

        unsigned h = ((unsigned)key * 2654435761u) & (HSIZE - 1);
        for (;;) {
            int cur = r_key[h];
            if (cur == key) break;
            if (cur == -1) {
                int prev = atomicCAS(&r_key[h], -1, key);
                if (prev == -1 || prev == key) break;
            }
            h = (h + 1) & (HSIZE - 1);
        }
        atomicAdd(&r_cnt[h], m);
        atomicMax(&r_rec[h], __float_as_uint(rec));
    }

    cluster.sync();   // all inserts complete

    // ---- rank 0: max-freq reduce, compute final values, push to owners ----
    if (seg == 0) {
        int mf = 0;
        #pragma unroll 4
        for (int i = tid; i < HSIZE; i += NT) mf = max(mf, h_cnt[i]);
        #pragma unroll
        for (int o = 16; o > 0; o >>= 1) mf = max(mf, __shfl_xor_sync(0xFFFFFFFFu, mf, o));
        if ((tid & 31) == 0) atomicMax(&s_maxcnt, mf);
        __syncthreads();

        const float inv = (*fw_p) / fmaxf((float)s_maxcnt, 1.0f);

        #pragma unroll 4
        for (int i = tid; i < HSIZE; i += NT) {
            const int key = h_key[i];
            if (key >= 0) {
                const float val = __uint_as_float(h_rec[i]) + (float)h_cnt[i] * inv;
                const int dseg = key / SEG_LEN;
                int*   dn = cluster.map_shared_rank(&s_n,   dseg);
                int*   dk = cluster.map_shared_rank(s_skey, dseg);
                float* dv = cluster.map_shared_rank(s_sval, dseg);
                const int pos = atomicAdd(dn, 1);
                dk[pos] = key;
                dv[pos] = val;
            }
        }
    }

    cluster.sync();   // pushed entries visible; also orders zero-stores before scatter

    // ---- scatter this segment's entries over the zeroed region ----
    const int n = s_n;
    for (int i = tid; i < n; i += NT)
        row[s_skey[i]] = s_sval[i];
}

extern "C" void kernel_launch(void* const* d_in, const int* in_sizes, int n_in,
                              void* d_out, int out_size)
{
    const int*   loc_seq = (const int*)  d_in[0];   // (B, L) int32
    const int*   mask    = (const int*)  d_in[1];   // (B, L) int32
    const float* rw      = (const float*)d_in[2];   // scalar
    const float* fw      = (const float*)d_in[3];   // scalar
    float*       out     = (float*)d_out;           // (B, N) float32

    fused_kernel<<<B_SZ * SEGS, NT>>>(loc_seq, mask, rw, fw, out);
}

// round 4
// speedup vs baseline: 2.6439x; 2.6439x over previous
#include <cuda_runtime.h>
#include <cstdint>

// Fixed shapes per reference: B=256, L=512, N=50000
constexpr int B_SZ   = 256;
constexpr int L_SEQ  = 512;
constexpr int N_LOC  = 50000;
constexpr int HSIZE  = 1024;           // hash slots (power of 2), load factor <= 0.5
constexpr int CAP    = 512;            // max distinct keys per row
constexpr int NT     = 256;
constexpr int NZ     = 1776;           // zeroing CTAs (12 * 148)
constexpr int TOTAL_F4 = (B_SZ * N_LOC) / 4;   // 3,200,000 float4

// Global scratch (__device__ arrays only — no runtime alloc)
__device__ int   g_n  [B_SZ];
__device__ int   g_key[B_SZ * CAP];
__device__ float g_val[B_SZ * CAP];

// ---------------------------------------------------------------------------
// Kernel 1: blocks [0, B_SZ) build per-row hash + compacted (key,val) list.
//           blocks [B_SZ, B_SZ+NZ) grid-stride zero-fill the output.
// Builders are first so they dispatch in wave 1 and hide under the memset.
// ---------------------------------------------------------------------------
__global__ __launch_bounds__(NT, 4)
void build_and_zero(const int* __restrict__ loc_seq,
                    const int* __restrict__ mask,
                    const float* __restrict__ rw_p,
                    const float* __restrict__ fw_p,
                    float* __restrict__ out)
{
    const int bid = blockIdx.x;
    const int tid = threadIdx.x;

    if (bid >= B_SZ) {
        // ---------------- pure memset path ----------------
        float4* o4 = reinterpret_cast<float4*>(out);
        const float4 z = make_float4(0.f, 0.f, 0.f, 0.f);
        const int stride = NZ * NT;
        #pragma unroll 4
        for (int i = (bid - B_SZ) * NT + tid; i < TOTAL_F4; i += stride)
            o4[i] = z;
        return;
    }

    // ---------------- builder path (one CTA per batch row) ----------------
    const int b = bid;

    __shared__ int      h_key[HSIZE];
    __shared__ int      h_cnt[HSIZE];
    __shared__ unsigned h_rec[HSIZE];   // float bits; all values >= 0
    __shared__ int      s_maxcnt;
    __shared__ int      s_n;

    #pragma unroll 4
    for (int i = tid; i < HSIZE; i += NT) {
        h_key[i] = -1;
        h_cnt[i] = 0;
        h_rec[i] = 0u;
    }
    if (tid == 0) { s_maxcnt = 0; s_n = 0; }
    __syncthreads();

    const float l2rw = log2f(*rw_p);

    const int2* lrow = reinterpret_cast<const int2*>(loc_seq + (size_t)b * L_SEQ);
    const int2* mrow = reinterpret_cast<const int2*>(mask    + (size_t)b * L_SEQ);
    const int2 lk = lrow[tid];
    const int2 mk = mrow[tid];

    #pragma unroll
    for (int j = 0; j < 2; j++) {
        const int t   = 2 * tid + j;
        const int key = (j == 0) ? lk.x : lk.y;
        const int m   = (j == 0) ? mk.x : mk.y;
        const float rec = m ? exp2f((float)(L_SEQ - 1 - t) * l2rw) : 0.0f;

        unsigned h = ((unsigned)key * 2654435761u) & (HSIZE - 1);
        for (;;) {
            int cur = h_key[h];
            if (cur == key) break;
            if (cur == -1) {
                int prev = atomicCAS(&h_key[h], -1, key);
                if (prev == -1 || prev == key) break;
            }
            h = (h + 1) & (HSIZE - 1);
        }
        atomicAdd(&h_cnt[h], m);
        atomicMax(&h_rec[h], __float_as_uint(rec));
    }
    __syncthreads();

    // block reduce: max frequency count
    int mf = 0;
    #pragma unroll 4
    for (int i = tid; i < HSIZE; i += NT) mf = max(mf, h_cnt[i]);
    #pragma unroll
    for (int o = 16; o > 0; o >>= 1) mf = max(mf, __shfl_xor_sync(0xFFFFFFFFu, mf, o));
    if ((tid & 31) == 0) atomicMax(&s_maxcnt, mf);
    __syncthreads();

    const float inv = (*fw_p) / fmaxf((float)s_maxcnt, 1.0f);

    // compact final values into the per-row list
    #pragma unroll 4
    for (int i = tid; i < HSIZE; i += NT) {
        const int key = h_key[i];
        if (key >= 0) {
            const float val = __uint_as_float(h_rec[i]) + (float)h_cnt[i] * inv;
            const int pos = atomicAdd(&s_n, 1);
            g_key[b * CAP + pos] = key;
            g_val[b * CAP + pos] = val;
        }
    }
    __syncthreads();
    if (tid == 0) g_n[b] = s_n;
}

// ---------------------------------------------------------------------------
// Kernel 2: one CTA per row, 512 threads; each thread scatters <= 1 entry.
// ---------------------------------------------------------------------------
__global__ __launch_bounds__(512, 2)
void scatter_kernel(float* __restrict__ out)
{
    const int b   = blockIdx.x;
    const int tid = threadIdx.x;
    const int n   = g_n[b];
    if (tid < n) {
        const int   key = g_key[b * CAP + tid];
        const float val = g_val[b * CAP + tid];
        out[(size_t)b * N_LOC + key] = val;
    }
}

extern "C" void kernel_launch(void* const* d_in, const int* in_sizes, int n_in,
                              void* d_out, int out_size)
{
    const int*   loc_seq = (const int*)  d_in[0];   // (B, L) int32
    const int*   mask    = (const int*)  d_in[1];   // (B, L) int32
    const float* rw      = (const float*)d_in[2];   // scalar
    const float* fw      = (const float*)d_in[3];   // scalar
    float*       out     = (float*)d_out;           // (B, N) float32

    build_and_zero<<<B_SZ + NZ, NT>>>(loc_seq, mask, rw, fw, out);
    scatter_kernel<<<B_SZ, 512>>>(out);
}

// round 5
// speedup vs baseline: 2.9639x; 1.1210x over previous
#include <cuda_runtime.h>
#include <cstdint>

// Fixed shapes per reference: B=256, L=512, N=50000
constexpr int B_SZ   = 256;
constexpr int L_SEQ  = 512;
constexpr int N_LOC  = 50000;               // 200,000 bytes per row
constexpr int HSIZE  = 1024;                // hash slots (pow2), load factor <= 0.5
constexpr int CAP    = 512;                 // max distinct keys per row
constexpr int NT     = 256;
constexpr int Z_PER_ROW = 4;                // zeroer CTAs per row (50,000 bytes each)
constexpr int N_ZERO = B_SZ * Z_PER_ROW;    // 1024
constexpr int ZBYTES = N_LOC * 4 / Z_PER_ROW; // 50,000 (multiple of 16)
constexpr int BUF_BYTES = 12288;            // smem zero buffer (multiple of 16)

__device__ int g_row_done[B_SZ];            // zero-initialized at module load

__device__ __forceinline__ uint32_t smem_u32(const void* p) {
    uint32_t a;
    asm("{ .reg .u64 t; cvta.to.shared.u64 t, %1; cvt.u32.u64 %0, t; }" : "=r"(a) : "l"(p));
    return a;
}

__global__ __launch_bounds__(NT)
void fused_kernel(const int* __restrict__ loc_seq,
                  const int* __restrict__ mask,
                  const float* __restrict__ rw_p,
                  const float* __restrict__ fw_p,
                  float* __restrict__ out)
{
    const int bid = blockIdx.x;
    const int tid = threadIdx.x;

    if (bid >= B_SZ) {
        // ================= zeroer path =================
        const int zi = bid - B_SZ;          // 0..1023
        const int b  = zi / Z_PER_ROW;
        const int q  = zi % Z_PER_ROW;

        __shared__ float4 buf[BUF_BYTES / 16];
        const float4 z = make_float4(0.f, 0.f, 0.f, 0.f);
        #pragma unroll
        for (int i = tid; i < BUF_BYTES / 16; i += NT) buf[i] = z;
        __syncthreads();
        // order generic smem writes before async-proxy (bulk copy) reads
        asm volatile("fence.proxy.async.shared::cta;" ::: "memory");

        if (tid == 0) {
            char* dst = (char*)out + (size_t)b * (N_LOC * 4) + (size_t)q * ZBYTES;
            uint32_t src = smem_u32(buf);
            int rem = ZBYTES;
            while (rem > 0) {
                int c = rem < BUF_BYTES ? rem : BUF_BYTES;
                asm volatile(
                    "cp.async.bulk.global.shared::cta.bulk_group [%0], [%1], %2;"
                    :: "l"(dst), "r"(src), "r"(c) : "memory");
                dst += c; rem -= c;
            }
            asm volatile("cp.async.bulk.commit_group;" ::: "memory");
            asm volatile("cp.async.bulk.wait_group 0;" ::: "memory");
            __threadfence();                      // make zero writes visible chip-wide
            atomicAdd(&g_row_done[b], 1);         // signal quarter complete
        }
        return;
    }

    // ================= builder path (one CTA per batch row) =================
    const int b = bid;

    __shared__ int      h_key[HSIZE];
    __shared__ int      h_cnt[HSIZE];
    __shared__ unsigned h_rec[HSIZE];   // float bits; all values >= 0
    __shared__ int      s_maxcnt;
    __shared__ int      s_n;
    __shared__ int      s_skey[CAP];
    __shared__ float    s_sval[CAP];

    #pragma unroll 4
    for (int i = tid; i < HSIZE; i += NT) {
        h_key[i] = -1;
        h_cnt[i] = 0;
        h_rec[i] = 0u;
    }
    if (tid == 0) { s_maxcnt = 0; s_n = 0; }
    __syncthreads();

    const float l2rw = log2f(*rw_p);

    const int2* lrow = reinterpret_cast<const int2*>(loc_seq + (size_t)b * L_SEQ);
    const int2* mrow = reinterpret_cast<const int2*>(mask    + (size_t)b * L_SEQ);
    const int2 lk = lrow[tid];
    const int2 mk = mrow[tid];

    #pragma unroll
    for (int j = 0; j < 2; j++) {
        const int t   = 2 * tid + j;
        const int key = (j == 0) ? lk.x : lk.y;
        const int m   = (j == 0) ? mk.x : mk.y;
        const float rec = m ? exp2f((float)(L_SEQ - 1 - t) * l2rw) : 0.0f;

        unsigned h = ((unsigned)key * 2654435761u) & (HSIZE - 1);
        for (;;) {
            int cur = h_key[h];
            if (cur == key) break;
            if (cur == -1) {
                int prev = atomicCAS(&h_key[h], -1, key);
                if (prev == -1 || prev == key) break;
            }
            h = (h + 1) & (HSIZE - 1);
        }
        atomicAdd(&h_cnt[h], m);
        atomicMax(&h_rec[h], __float_as_uint(rec));
    }
    __syncthreads();

    // block reduce: max frequency count
    int mf = 0;
    #pragma unroll 4
    for (int i = tid; i < HSIZE; i += NT) mf = max(mf, h_cnt[i]);
    #pragma unroll
    for (int o = 16; o > 0; o >>= 1) mf = max(mf, __shfl_xor_sync(0xFFFFFFFFu, mf, o));
    if ((tid & 31) == 0) atomicMax(&s_maxcnt, mf);
    __syncthreads();

    const float inv = (*fw_p) / fmaxf((float)s_maxcnt, 1.0f);

    // compact final values into smem list
    #pragma unroll 4
    for (int i = tid; i < HSIZE; i += NT) {
        const int key = h_key[i];
        if (key >= 0) {
            const float val = __uint_as_float(h_rec[i]) + (float)h_cnt[i] * inv;
            const int pos = atomicAdd(&s_n, 1);
            s_skey[pos] = key;
            s_sval[pos] = val;
        }
    }
    __syncthreads();

    // wait for this row's zeroers, then scatter directly from smem
    if (tid == 0) {
        while (atomicAdd(&g_row_done[b], 0) != Z_PER_ROW) { }
        __threadfence();                  // acquire: zero stores visible before ours
        g_row_done[b] = 0;                // reset for next graph replay (sole consumer)
    }
    __syncthreads();

    float* row = out + (size_t)b * N_LOC;
    const int n = s_n;
    for (int i = tid; i < n; i += NT)
        row[s_skey[i]] = s_sval[i];
}

extern "C" void kernel_launch(void* const* d_in, const int* in_sizes, int n_in,
                              void* d_out, int out_size)
{
    const int*   loc_seq = (const int*)  d_in[0];   // (B, L) int32
    const int*   mask    = (const int*)  d_in[1];   // (B, L) int32
    const float* rw      = (const float*)d_in[2];   // scalar
    const float* fw      = (const float*)d_in[3];   // scalar
    float*       out     = (float*)d_out;           // (B, N) float32

    fused_kernel<<<B_SZ + N_ZERO, NT>>>(loc_seq, mask, rw, fw, out);
}